// round 1
// baseline (speedup 1.0000x reference)
#include <cuda_runtime.h>

// GNN: logits = relu( (relu(xW0^T+b0) + norm-scatter) W1^T + b1 ) Wc^T + bc
// 3 kernels: gemm1 (+zero agg/deg), edge scatter (vector RED), fused gemm2+classifier.

#define DIMK 128
#define NCLS 4
#define BM   64
#define XS_PITCH 132
#define MAXN 100000

__device__ __align__(16) float g_h0[(size_t)MAXN * DIMK];
__device__ __align__(16) float g_agg[(size_t)MAXN * DIMK];
__device__ __align__(16) float g_deg[MAXN];

typedef unsigned long long u64;

__device__ __forceinline__ u64 pk2(float lo, float hi) {
    u64 r; asm("mov.b64 %0, {%1, %2};" : "=l"(r) : "f"(lo), "f"(hi)); return r;
}
__device__ __forceinline__ u64 fma2(u64 a, u64 b, u64 c) {
    u64 d; asm("fma.rn.f32x2 %0, %1, %2, %3;" : "=l"(d) : "l"(a), "l"(b), "l"(c)); return d;
}
__device__ __forceinline__ float2 upk2(u64 v) {
    float lo, hi; asm("mov.b64 {%0, %1}, %2;" : "=f"(lo), "=f"(hi) : "l"(v));
    float2 f; f.x = lo; f.y = hi; return f;
}

// ---------------------------------------------------------------------------
// GEMM1: h0 = relu(x @ W0^T + b0). Also zeroes agg/deg rows for this block.
// Block: 256 threads, 64 rows. SMEM: Ws[k][j] (transposed W), xs[64][132].
// Thread tile: 4 rows x 8 cols, accumulated as 4x4 packed f32x2.
// ---------------------------------------------------------------------------
extern "C" __global__ __launch_bounds__(256, 2)
void k_gemm1(const float* __restrict__ x, const float* __restrict__ W0,
             const float* __restrict__ b0, int n)
{
    extern __shared__ float smem[];
    float* Ws = smem;                 // 128*128
    float* xs = smem + DIMK * DIMK;   // 64*132
    const int tid  = threadIdx.x;
    const int row0 = blockIdx.x * BM;

    // Transpose W0 -> Ws[k][j]. Coalesced-j scalar smem stores (conflict-free).
#pragma unroll
    for (int it = 0; it < 16; ++it) {
        int idx = tid + it * 256;     // 0..4095
        int j   = idx & 127;
        int k4  = (idx >> 7) * 4;
        float4 w = *(const float4*)&W0[j * DIMK + k4];
        Ws[(k4 + 0) * DIMK + j] = w.x;
        Ws[(k4 + 1) * DIMK + j] = w.y;
        Ws[(k4 + 2) * DIMK + j] = w.z;
        Ws[(k4 + 3) * DIMK + j] = w.w;
    }
    // Load x tile + zero agg rows.
#pragma unroll
    for (int it = 0; it < 8; ++it) {
        int idx = tid + it * 256;     // float4 units, 0..2047
        int r   = idx >> 5;
        int c4  = (idx & 31) * 4;
        int grow = row0 + r;
        float4 v = make_float4(0.f, 0.f, 0.f, 0.f);
        if (grow < n) {
            v = *(const float4*)&x[(size_t)grow * DIMK + c4];
            *(float4*)&g_agg[(size_t)grow * DIMK + c4] = make_float4(0.f, 0.f, 0.f, 0.f);
        }
        *(float4*)&xs[r * XS_PITCH + c4] = v;
    }
    if (tid < BM && row0 + tid < n) g_deg[row0 + tid] = 0.f;
    __syncthreads();

    const int colg = tid & 15, rowg = tid >> 4;
    const int c0 = colg * 8, r0 = rowg * 4;
    const u64* Ws2 = (const u64*)Ws;

    u64 acc[4][4];
#pragma unroll
    for (int i = 0; i < 4; ++i)
#pragma unroll
        for (int u = 0; u < 4; ++u) acc[i][u] = 0ull;

#pragma unroll 4
    for (int k = 0; k < DIMK; ++k) {
        u64 xx[4];
#pragma unroll
        for (int i = 0; i < 4; ++i) {
            float xv = xs[(r0 + i) * XS_PITCH + k];
            xx[i] = pk2(xv, xv);
        }
        u64 wv[4];
#pragma unroll
        for (int u = 0; u < 4; ++u) wv[u] = Ws2[k * (DIMK / 2) + colg * 4 + u];
#pragma unroll
        for (int i = 0; i < 4; ++i)
#pragma unroll
            for (int u = 0; u < 4; ++u)
                acc[i][u] = fma2(xx[i], wv[u], acc[i][u]);
    }

    float bb[8];
#pragma unroll
    for (int u = 0; u < 8; ++u) bb[u] = b0[c0 + u];
#pragma unroll
    for (int i = 0; i < 4; ++i) {
        int grow = row0 + r0 + i;
        if (grow < n) {
            float4 o0, o1; float2 p;
            p = upk2(acc[i][0]); o0.x = fmaxf(p.x + bb[0], 0.f); o0.y = fmaxf(p.y + bb[1], 0.f);
            p = upk2(acc[i][1]); o0.z = fmaxf(p.x + bb[2], 0.f); o0.w = fmaxf(p.y + bb[3], 0.f);
            p = upk2(acc[i][2]); o1.x = fmaxf(p.x + bb[4], 0.f); o1.y = fmaxf(p.y + bb[5], 0.f);
            p = upk2(acc[i][3]); o1.z = fmaxf(p.x + bb[6], 0.f); o1.w = fmaxf(p.y + bb[7], 0.f);
            *(float4*)&g_h0[(size_t)grow * DIMK + c0]     = o0;
            *(float4*)&g_h0[(size_t)grow * DIMK + c0 + 4] = o1;
        }
    }
}

// ---------------------------------------------------------------------------
// Scatter: one warp per edge. lane l moves float4 l of the 128-float row.
// agg[row] += h0[col] via red.global.add.v4.f32; deg[row] += 1 (lane 0).
// ---------------------------------------------------------------------------
extern "C" __global__ void k_scatter(const int* __restrict__ ei, int nE)
{
    int gw   = (int)((blockIdx.x * blockDim.x + threadIdx.x) >> 5);
    int lane = threadIdx.x & 31;
    if (gw >= nE) return;
    int dst = ei[gw];        // edge_index[0][e] -> segment id
    int src = ei[nE + gw];   // edge_index[1][e] -> gathered features
    float4 v = *(const float4*)&g_h0[(size_t)src * DIMK + lane * 4];
    float* p = &g_agg[(size_t)dst * DIMK + lane * 4];
    asm volatile("red.global.add.v4.f32 [%0], {%1,%2,%3,%4};"
                 :: "l"(p), "f"(v.x), "f"(v.y), "f"(v.z), "f"(v.w) : "memory");
    if (lane == 0) atomicAdd(&g_deg[dst], 1.0f);
}

// ---------------------------------------------------------------------------
// GEMM2 fused: hin = h0 + agg/max(deg,1); h = relu(hin@W1^T + b1);
// logits = h@Wc^T + bc. Same tiling as gemm1 + in-register classifier with
// 16-lane shfl reduction.
// ---------------------------------------------------------------------------
extern "C" __global__ __launch_bounds__(256, 2)
void k_gemm2(const float* __restrict__ W1, const float* __restrict__ b1,
             const float* __restrict__ Wc, const float* __restrict__ bc,
             float* __restrict__ out, int n)
{
    extern __shared__ float smem[];
    float* Ws  = smem;                       // 128*128
    float* xs  = smem + DIMK * DIMK;         // 64*132
    float* Wcs = xs + BM * XS_PITCH;         // 4*128
    const int tid  = threadIdx.x;
    const int row0 = blockIdx.x * BM;

#pragma unroll
    for (int it = 0; it < 16; ++it) {
        int idx = tid + it * 256;
        int j   = idx & 127;
        int k4  = (idx >> 7) * 4;
        float4 w = *(const float4*)&W1[j * DIMK + k4];
        Ws[(k4 + 0) * DIMK + j] = w.x;
        Ws[(k4 + 1) * DIMK + j] = w.y;
        Ws[(k4 + 2) * DIMK + j] = w.z;
        Ws[(k4 + 3) * DIMK + j] = w.w;
    }
    if (tid < 128) {
        float4 w = *(const float4*)&Wc[tid * 4];
        *(float4*)&Wcs[tid * 4] = w;
    }
    // hin tile: h0 + agg * (1/max(deg,1))
#pragma unroll
    for (int it = 0; it < 8; ++it) {
        int idx = tid + it * 256;
        int r   = idx >> 5;
        int c4  = (idx & 31) * 4;
        int grow = row0 + r;
        float4 v = make_float4(0.f, 0.f, 0.f, 0.f);
        if (grow < n) {
            float4 hv = *(const float4*)&g_h0[(size_t)grow * DIMK + c4];
            float4 av = *(const float4*)&g_agg[(size_t)grow * DIMK + c4];
            float inv = 1.0f / fmaxf(g_deg[grow], 1.0f);
            v.x = hv.x + av.x * inv;
            v.y = hv.y + av.y * inv;
            v.z = hv.z + av.z * inv;
            v.w = hv.w + av.w * inv;
        }
        *(float4*)&xs[r * XS_PITCH + c4] = v;
    }
    __syncthreads();

    const int colg = tid & 15, rowg = tid >> 4;
    const int c0 = colg * 8, r0 = rowg * 4;
    const u64* Ws2 = (const u64*)Ws;

    u64 acc[4][4];
#pragma unroll
    for (int i = 0; i < 4; ++i)
#pragma unroll
        for (int u = 0; u < 4; ++u) acc[i][u] = 0ull;

#pragma unroll 4
    for (int k = 0; k < DIMK; ++k) {
        u64 xx[4];
#pragma unroll
        for (int i = 0; i < 4; ++i) {
            float xv = xs[(r0 + i) * XS_PITCH + k];
            xx[i] = pk2(xv, xv);
        }
        u64 wv[4];
#pragma unroll
        for (int u = 0; u < 4; ++u) wv[u] = Ws2[k * (DIMK / 2) + colg * 4 + u];
#pragma unroll
        for (int i = 0; i < 4; ++i)
#pragma unroll
            for (int u = 0; u < 4; ++u)
                acc[i][u] = fma2(xx[i], wv[u], acc[i][u]);
    }

    float bb[8];
#pragma unroll
    for (int u = 0; u < 8; ++u) bb[u] = b1[c0 + u];

    float part[4][4];
#pragma unroll
    for (int i = 0; i < 4; ++i)
#pragma unroll
        for (int c = 0; c < 4; ++c) part[i][c] = 0.f;

#pragma unroll
    for (int i = 0; i < 4; ++i) {
        float h[8]; float2 p;
        p = upk2(acc[i][0]); h[0] = fmaxf(p.x + bb[0], 0.f); h[1] = fmaxf(p.y + bb[1], 0.f);
        p = upk2(acc[i][1]); h[2] = fmaxf(p.x + bb[2], 0.f); h[3] = fmaxf(p.y + bb[3], 0.f);
        p = upk2(acc[i][2]); h[4] = fmaxf(p.x + bb[4], 0.f); h[5] = fmaxf(p.y + bb[5], 0.f);
        p = upk2(acc[i][3]); h[6] = fmaxf(p.x + bb[6], 0.f); h[7] = fmaxf(p.y + bb[7], 0.f);
#pragma unroll
        for (int u = 0; u < 8; ++u) {
            float hv = h[u];
            part[i][0] += hv * Wcs[0 * DIMK + c0 + u];
            part[i][1] += hv * Wcs[1 * DIMK + c0 + u];
            part[i][2] += hv * Wcs[2 * DIMK + c0 + u];
            part[i][3] += hv * Wcs[3 * DIMK + c0 + u];
        }
    }
    // Reduce over the 16 col-group lanes (lane&15 halves of each warp).
#pragma unroll
    for (int i = 0; i < 4; ++i)
#pragma unroll
        for (int c = 0; c < 4; ++c) {
            float v = part[i][c];
            v += __shfl_xor_sync(0xffffffffu, v, 8);
            v += __shfl_xor_sync(0xffffffffu, v, 4);
            v += __shfl_xor_sync(0xffffffffu, v, 2);
            v += __shfl_xor_sync(0xffffffffu, v, 1);
            part[i][c] = v;
        }
    if (colg == 0) {
        float4 bcv = *(const float4*)&bc[0];
#pragma unroll
        for (int i = 0; i < 4; ++i) {
            int grow = row0 + r0 + i;
            if (grow < n) {
                float4 o;
                o.x = part[i][0] + bcv.x;
                o.y = part[i][1] + bcv.y;
                o.z = part[i][2] + bcv.z;
                o.w = part[i][3] + bcv.w;
                *(float4*)&out[(size_t)grow * NCLS] = o;
            }
        }
    }
}

extern "C" void kernel_launch(void* const* d_in, const int* in_sizes, int n_in,
                              void* d_out, int out_size)
{
    const float* x  = (const float*)d_in[0];
    const int*   ei = (const int*)  d_in[1];
    const float* W0 = (const float*)d_in[2];
    const float* b0 = (const float*)d_in[3];
    const float* W1 = (const float*)d_in[4];
    const float* b1 = (const float*)d_in[5];
    const float* Wc = (const float*)d_in[6];
    const float* bc = (const float*)d_in[7];
    float* out = (float*)d_out;

    int n  = in_sizes[0] / DIMK;     // 100000
    int nE = in_sizes[1] / 2;        // 800000

    int smem1 = (DIMK * DIMK + BM * XS_PITCH) * (int)sizeof(float);
    int smem2 = (DIMK * DIMK + BM * XS_PITCH + NCLS * DIMK) * (int)sizeof(float);
    cudaFuncSetAttribute(k_gemm1, cudaFuncAttributeMaxDynamicSharedMemorySize, smem1);
    cudaFuncSetAttribute(k_gemm2, cudaFuncAttributeMaxDynamicSharedMemorySize, smem2);

    int grid = (n + BM - 1) / BM;
    k_gemm1<<<grid, 256, smem1>>>(x, W0, b0, n);

    long long tthreads = (long long)nE * 32;
    int sblocks = (int)((tthreads + 255) / 256);
    k_scatter<<<sblocks, 256>>>(ei, nE);

    k_gemm2<<<grid, 256, smem2>>>(W1, b1, Wc, bc, out, n);
}

// round 2
// speedup vs baseline: 1.0677x; 1.0677x over previous
#include <cuda_runtime.h>

// GNN: logits = relu( (relu(xW0^T+b0) + norm-scatter) W1^T + b1 ) Wc^T + bc
// 3 kernels: gemm1 (+zero agg/deg), edge scatter (vector RED), fused gemm2+classifier.
// GEMM: 128x128 block tile, 256 threads, 8x8 micro-tile, f32x2 packed FMA,
// conflict-free smem layout (W transposed k-major, contiguous 128B per warp).

#define DIMK 128
#define NCLS 4
#define BM   128
#define XS_P 132
#define MAXN 100000

__device__ __align__(16) float g_h0[(size_t)MAXN * DIMK];
__device__ __align__(16) float g_agg[(size_t)MAXN * DIMK];
__device__ __align__(16) float g_deg[MAXN];

typedef unsigned long long u64;

__device__ __forceinline__ u64 pk2(float lo, float hi) {
    u64 r; asm("mov.b64 %0, {%1, %2};" : "=l"(r) : "f"(lo), "f"(hi)); return r;
}
__device__ __forceinline__ u64 fma2(u64 a, u64 b, u64 c) {
    u64 d; asm("fma.rn.f32x2 %0, %1, %2, %3;" : "=l"(d) : "l"(a), "l"(b), "l"(c)); return d;
}
__device__ __forceinline__ float2 upk2(u64 v) {
    float lo, hi; asm("mov.b64 {%0, %1}, %2;" : "=f"(lo), "=f"(hi) : "l"(v));
    float2 f; f.x = lo; f.y = hi; return f;
}

// ---------------------------------------------------------------------------
// GEMM1: h0 = relu(x @ W0^T + b0). Also zeroes agg/deg rows for this block.
// ---------------------------------------------------------------------------
extern "C" __global__ __launch_bounds__(256)
void k_gemm1(const float* __restrict__ x, const float* __restrict__ W0,
             const float* __restrict__ b0, int n)
{
    extern __shared__ float smem[];
    float* Ws = smem;                 // [128 k][128 c]
    float* xs = smem + DIMK * DIMK;   // [128 r][132]
    const int tid  = threadIdx.x;
    const int row0 = blockIdx.x * BM;

    // Transpose W0 -> Ws[k][c]. Stores: consecutive lanes -> consecutive c: conflict-free.
#pragma unroll
    for (int it = 0; it < 16; ++it) {
        int idx = tid + it * 256;     // 0..4095 float4 units
        int j   = idx & 127;          // output col c
        int k4  = (idx >> 7) * 4;
        float4 w = *(const float4*)&W0[j * DIMK + k4];
        Ws[(k4 + 0) * DIMK + j] = w.x;
        Ws[(k4 + 1) * DIMK + j] = w.y;
        Ws[(k4 + 2) * DIMK + j] = w.z;
        Ws[(k4 + 3) * DIMK + j] = w.w;
    }
    // x tile row-major (pitch 132) + zero agg rows.
#pragma unroll
    for (int it = 0; it < 16; ++it) {
        int idx = tid + it * 256;     // float4 units, 0..4095
        int r   = idx >> 5;
        int c4  = (idx & 31) * 4;
        int grow = row0 + r;
        float4 v = make_float4(0.f, 0.f, 0.f, 0.f);
        if (grow < n) {
            v = *(const float4*)&x[(size_t)grow * DIMK + c4];
            *(float4*)&g_agg[(size_t)grow * DIMK + c4] = make_float4(0.f, 0.f, 0.f, 0.f);
        }
        *(float4*)&xs[r * XS_P + c4] = v;
    }
    if (tid < BM && row0 + tid < n) g_deg[row0 + tid] = 0.f;
    __syncthreads();

    const int warp = tid >> 5, lane = tid & 31;
    const int warp_m = warp & 3, warp_n = warp >> 2;
    const int rgrp = lane >> 3, cgrp = lane & 7;
    const int r_base = warp_m * 32 + rgrp * 4;
    const int c_base = warp_n * 64 + cgrp * 4;

    u64 acc[8][4];
#pragma unroll
    for (int i = 0; i < 8; ++i)
#pragma unroll
        for (int u = 0; u < 4; ++u) acc[i][u] = 0ull;

#pragma unroll 2
    for (int k = 0; k < DIMK; ++k) {
        const float* wsk = &Ws[k * DIMK];
        ulonglong2 wa = *(const ulonglong2*)&wsk[c_base];
        ulonglong2 wb = *(const ulonglong2*)&wsk[c_base + 32];
#pragma unroll
        for (int i = 0; i < 4; ++i) {
            float xv0 = xs[(r_base + i) * XS_P + k];
            float xv1 = xs[(r_base + 16 + i) * XS_P + k];
            u64 x0 = pk2(xv0, xv0);
            u64 x1 = pk2(xv1, xv1);
            acc[i][0] = fma2(x0, wa.x, acc[i][0]);
            acc[i][1] = fma2(x0, wa.y, acc[i][1]);
            acc[i][2] = fma2(x0, wb.x, acc[i][2]);
            acc[i][3] = fma2(x0, wb.y, acc[i][3]);
            acc[i + 4][0] = fma2(x1, wa.x, acc[i + 4][0]);
            acc[i + 4][1] = fma2(x1, wa.y, acc[i + 4][1]);
            acc[i + 4][2] = fma2(x1, wb.x, acc[i + 4][2]);
            acc[i + 4][3] = fma2(x1, wb.y, acc[i + 4][3]);
        }
    }

    float4 ba = *(const float4*)&b0[c_base];
    float4 bb = *(const float4*)&b0[c_base + 32];
#pragma unroll
    for (int i = 0; i < 8; ++i) {
        int r = r_base + (i & 3) + ((i >> 2) << 4);
        int grow = row0 + r;
        if (grow < n) {
            float2 p0 = upk2(acc[i][0]), p1 = upk2(acc[i][1]);
            float2 p2 = upk2(acc[i][2]), p3 = upk2(acc[i][3]);
            float4 oa, ob;
            oa.x = fmaxf(p0.x + ba.x, 0.f); oa.y = fmaxf(p0.y + ba.y, 0.f);
            oa.z = fmaxf(p1.x + ba.z, 0.f); oa.w = fmaxf(p1.y + ba.w, 0.f);
            ob.x = fmaxf(p2.x + bb.x, 0.f); ob.y = fmaxf(p2.y + bb.y, 0.f);
            ob.z = fmaxf(p3.x + bb.z, 0.f); ob.w = fmaxf(p3.y + bb.w, 0.f);
            *(float4*)&g_h0[(size_t)grow * DIMK + c_base]      = oa;
            *(float4*)&g_h0[(size_t)grow * DIMK + c_base + 32] = ob;
        }
    }
}

// ---------------------------------------------------------------------------
// Scatter: one warp per edge; lane l moves float4 l of the 128-float row.
// ---------------------------------------------------------------------------
extern "C" __global__ void k_scatter(const int* __restrict__ ei, int nE)
{
    int gw   = (int)((blockIdx.x * blockDim.x + threadIdx.x) >> 5);
    int lane = threadIdx.x & 31;
    if (gw >= nE) return;
    int dst = ei[gw];        // edge_index[0][e] -> segment id
    int src = ei[nE + gw];   // edge_index[1][e] -> gathered features
    float4 v = *(const float4*)&g_h0[(size_t)src * DIMK + lane * 4];
    float* p = &g_agg[(size_t)dst * DIMK + lane * 4];
    asm volatile("red.global.add.v4.f32 [%0], {%1,%2,%3,%4};"
                 :: "l"(p), "f"(v.x), "f"(v.y), "f"(v.z), "f"(v.w) : "memory");
    if (lane == 0) atomicAdd(&g_deg[dst], 1.0f);
}

// ---------------------------------------------------------------------------
// GEMM2 fused: hin = h0 + agg/max(deg,1); h = relu(hin@W1^T + b1);
// logits = h@Wc^T + bc (classifier reduced via shfl + smem atomics).
// ---------------------------------------------------------------------------
extern "C" __global__ __launch_bounds__(256)
void k_gemm2(const float* __restrict__ W1, const float* __restrict__ b1,
             const float* __restrict__ Wc, const float* __restrict__ bc,
             float* __restrict__ out, int n)
{
    extern __shared__ float smem[];
    float* Ws  = smem;                       // 128*128
    float* xs  = smem + DIMK * DIMK;         // 128*132
    float* Wcs = xs + BM * XS_P;             // 4*128
    float* red = Wcs + NCLS * DIMK;          // 128*4
    const int tid  = threadIdx.x;
    const int row0 = blockIdx.x * BM;

#pragma unroll
    for (int it = 0; it < 16; ++it) {
        int idx = tid + it * 256;
        int j   = idx & 127;
        int k4  = (idx >> 7) * 4;
        float4 w = *(const float4*)&W1[j * DIMK + k4];
        Ws[(k4 + 0) * DIMK + j] = w.x;
        Ws[(k4 + 1) * DIMK + j] = w.y;
        Ws[(k4 + 2) * DIMK + j] = w.z;
        Ws[(k4 + 3) * DIMK + j] = w.w;
    }
    if (tid < 128) {
        float4 w = *(const float4*)&Wc[tid * 4];
        *(float4*)&Wcs[tid * 4] = w;
    }
#pragma unroll
    for (int idx = tid; idx < BM * NCLS; idx += 256)
        red[idx] = bc[idx & 3];

    // hin tile: h0 + agg * (1/max(deg,1))
#pragma unroll
    for (int it = 0; it < 16; ++it) {
        int idx = tid + it * 256;
        int r   = idx >> 5;
        int c4  = (idx & 31) * 4;
        int grow = row0 + r;
        float4 v = make_float4(0.f, 0.f, 0.f, 0.f);
        if (grow < n) {
            float4 hv = *(const float4*)&g_h0[(size_t)grow * DIMK + c4];
            float4 av = *(const float4*)&g_agg[(size_t)grow * DIMK + c4];
            float inv = 1.0f / fmaxf(g_deg[grow], 1.0f);
            v.x = hv.x + av.x * inv;
            v.y = hv.y + av.y * inv;
            v.z = hv.z + av.z * inv;
            v.w = hv.w + av.w * inv;
        }
        *(float4*)&xs[r * XS_P + c4] = v;
    }
    __syncthreads();

    const int warp = tid >> 5, lane = tid & 31;
    const int warp_m = warp & 3, warp_n = warp >> 2;
    const int rgrp = lane >> 3, cgrp = lane & 7;
    const int r_base = warp_m * 32 + rgrp * 4;
    const int c_base = warp_n * 64 + cgrp * 4;

    u64 acc[8][4];
#pragma unroll
    for (int i = 0; i < 8; ++i)
#pragma unroll
        for (int u = 0; u < 4; ++u) acc[i][u] = 0ull;

#pragma unroll 2
    for (int k = 0; k < DIMK; ++k) {
        const float* wsk = &Ws[k * DIMK];
        ulonglong2 wa = *(const ulonglong2*)&wsk[c_base];
        ulonglong2 wb = *(const ulonglong2*)&wsk[c_base + 32];
#pragma unroll
        for (int i = 0; i < 4; ++i) {
            float xv0 = xs[(r_base + i) * XS_P + k];
            float xv1 = xs[(r_base + 16 + i) * XS_P + k];
            u64 x0 = pk2(xv0, xv0);
            u64 x1 = pk2(xv1, xv1);
            acc[i][0] = fma2(x0, wa.x, acc[i][0]);
            acc[i][1] = fma2(x0, wa.y, acc[i][1]);
            acc[i][2] = fma2(x0, wb.x, acc[i][2]);
            acc[i][3] = fma2(x0, wb.y, acc[i][3]);
            acc[i + 4][0] = fma2(x1, wa.x, acc[i + 4][0]);
            acc[i + 4][1] = fma2(x1, wa.y, acc[i + 4][1]);
            acc[i + 4][2] = fma2(x1, wb.x, acc[i + 4][2]);
            acc[i + 4][3] = fma2(x1, wb.y, acc[i + 4][3]);
        }
    }

    float4 ba = *(const float4*)&b1[c_base];
    float4 bb = *(const float4*)&b1[c_base + 32];

    float part[8][NCLS];
#pragma unroll
    for (int i = 0; i < 8; ++i)
#pragma unroll
        for (int c = 0; c < NCLS; ++c) part[i][c] = 0.f;

#pragma unroll
    for (int i = 0; i < 8; ++i) {
        float h[8];
        float2 p0 = upk2(acc[i][0]), p1 = upk2(acc[i][1]);
        float2 p2 = upk2(acc[i][2]), p3 = upk2(acc[i][3]);
        h[0] = fmaxf(p0.x + ba.x, 0.f); h[1] = fmaxf(p0.y + ba.y, 0.f);
        h[2] = fmaxf(p1.x + ba.z, 0.f); h[3] = fmaxf(p1.y + ba.w, 0.f);
        h[4] = fmaxf(p2.x + bb.x, 0.f); h[5] = fmaxf(p2.y + bb.y, 0.f);
        h[6] = fmaxf(p3.x + bb.z, 0.f); h[7] = fmaxf(p3.y + bb.w, 0.f);
#pragma unroll
        for (int c = 0; c < NCLS; ++c) {
            const float* wrow = &Wcs[c * DIMK];
            float s = 0.f;
#pragma unroll
            for (int u = 0; u < 4; ++u) s += h[u] * wrow[c_base + u];
#pragma unroll
            for (int u = 0; u < 4; ++u) s += h[4 + u] * wrow[c_base + 32 + u];
            part[i][c] = s;
        }
    }
    // Reduce over the 8 cgrp lanes.
#pragma unroll
    for (int i = 0; i < 8; ++i)
#pragma unroll
        for (int c = 0; c < NCLS; ++c) {
            float v = part[i][c];
            v += __shfl_xor_sync(0xffffffffu, v, 1);
            v += __shfl_xor_sync(0xffffffffu, v, 2);
            v += __shfl_xor_sync(0xffffffffu, v, 4);
            part[i][c] = v;
        }
    if (cgrp == 0) {
#pragma unroll
        for (int i = 0; i < 8; ++i) {
            int r = r_base + (i & 3) + ((i >> 2) << 4);
#pragma unroll
            for (int c = 0; c < NCLS; ++c)
                atomicAdd(&red[r * NCLS + c], part[i][c]);
        }
    }
    __syncthreads();
    if (tid < BM) {
        int grow = row0 + tid;
        if (grow < n) {
            float4 o = *(const float4*)&red[tid * NCLS];
            *(float4*)&out[(size_t)grow * NCLS] = o;
        }
    }
}

extern "C" void kernel_launch(void* const* d_in, const int* in_sizes, int n_in,
                              void* d_out, int out_size)
{
    const float* x  = (const float*)d_in[0];
    const int*   ei = (const int*)  d_in[1];
    const float* W0 = (const float*)d_in[2];
    const float* b0 = (const float*)d_in[3];
    const float* W1 = (const float*)d_in[4];
    const float* b1 = (const float*)d_in[5];
    const float* Wc = (const float*)d_in[6];
    const float* bc = (const float*)d_in[7];
    float* out = (float*)d_out;

    int n  = in_sizes[0] / DIMK;     // 100000
    int nE = in_sizes[1] / 2;        // 800000

    int smem1 = (DIMK * DIMK + BM * XS_P) * (int)sizeof(float);
    int smem2 = (DIMK * DIMK + BM * XS_P + NCLS * DIMK + BM * NCLS) * (int)sizeof(float);
    cudaFuncSetAttribute(k_gemm1, cudaFuncAttributeMaxDynamicSharedMemorySize, smem1);
    cudaFuncSetAttribute(k_gemm2, cudaFuncAttributeMaxDynamicSharedMemorySize, smem2);

    int grid = (n + BM - 1) / BM;
    k_gemm1<<<grid, 256, smem1>>>(x, W0, b0, n);

    long long tthreads = (long long)nE * 32;
    int sblocks = (int)((tthreads + 255) / 256);
    k_scatter<<<sblocks, 256>>>(ei, nE);

    k_gemm2<<<grid, 256, smem2>>>(W1, b1, Wc, bc, out, n);
}

// round 4
// speedup vs baseline: 1.1244x; 1.0531x over previous
#include <cuda_runtime.h>

// GNN: logits = relu( (relu(xW0^T+b0) + norm-scatter) W1^T + b1 ) Wc^T + bc
// 3 kernels: gemm1 (+zero agg/deg), edge scatter (vector RED), fused gemm2+classifier.
// GEMM: 128x128 block tile, 512 threads (16 warps -> 4/SMSP), 4x8 micro-tile,
// f32x2 packed FMA, conflict-free smem layout.

#define DIMK 128
#define NCLS 4
#define BM   128
#define XS_P 132
#define MAXN 100000

__device__ __align__(16) float g_h0[(size_t)MAXN * DIMK];
__device__ __align__(16) float g_agg[(size_t)MAXN * DIMK];
__device__ __align__(16) float g_deg[MAXN];

typedef unsigned long long u64;

__device__ __forceinline__ u64 pk2(float lo, float hi) {
    u64 r; asm("mov.b64 %0, {%1, %2};" : "=l"(r) : "f"(lo), "f"(hi)); return r;
}
__device__ __forceinline__ u64 fma2(u64 a, u64 b, u64 c) {
    u64 d; asm("fma.rn.f32x2 %0, %1, %2, %3;" : "=l"(d) : "l"(a), "l"(b), "l"(c)); return d;
}
__device__ __forceinline__ float2 upk2(u64 v) {
    float lo, hi; asm("mov.b64 {%0, %1}, %2;" : "=f"(lo), "=f"(hi) : "l"(v));
    float2 f; f.x = lo; f.y = hi; return f;
}

// ---------------------------------------------------------------------------
// GEMM1: h0 = relu(x @ W0^T + b0). Also zeroes agg/deg rows for this block.
// ---------------------------------------------------------------------------
extern "C" __global__ __launch_bounds__(512)
void k_gemm1(const float* __restrict__ x, const float* __restrict__ W0,
             const float* __restrict__ b0, int n)
{
    extern __shared__ float smem[];
    float* Ws = smem;                 // [128 k][128 c]
    float* xs = smem + DIMK * DIMK;   // [128 r][132]
    const int tid  = threadIdx.x;
    const int row0 = blockIdx.x * BM;

    // Transpose W0 -> Ws[k][c]. Consecutive lanes -> consecutive c: conflict-free.
#pragma unroll
    for (int it = 0; it < 8; ++it) {
        int idx = tid + it * 512;     // 0..4095 float4 units
        int j   = idx & 127;          // output col c
        int k4  = (idx >> 7) * 4;
        float4 w = *(const float4*)&W0[j * DIMK + k4];
        Ws[(k4 + 0) * DIMK + j] = w.x;
        Ws[(k4 + 1) * DIMK + j] = w.y;
        Ws[(k4 + 2) * DIMK + j] = w.z;
        Ws[(k4 + 3) * DIMK + j] = w.w;
    }
    // x tile row-major (pitch 132) + zero agg rows.
#pragma unroll
    for (int it = 0; it < 8; ++it) {
        int idx = tid + it * 512;     // float4 units, 0..4095
        int r   = idx >> 5;
        int c4  = (idx & 31) * 4;
        int grow = row0 + r;
        float4 v = make_float4(0.f, 0.f, 0.f, 0.f);
        if (grow < n) {
            v = *(const float4*)&x[(size_t)grow * DIMK + c4];
            *(float4*)&g_agg[(size_t)grow * DIMK + c4] = make_float4(0.f, 0.f, 0.f, 0.f);
        }
        *(float4*)&xs[r * XS_P + c4] = v;
    }
    if (tid < BM && row0 + tid < n) g_deg[row0 + tid] = 0.f;
    __syncthreads();

    const int warp = tid >> 5, lane = tid & 31;
    const int warp_m = warp & 3, warp_n = warp >> 2;
    const int rgrp = lane >> 2, cgrp = lane & 3;
    const int r_base = warp_m * 32 + rgrp * 4;
    const int c_base = warp_n * 32 + cgrp * 8;

    u64 acc[4][4];
#pragma unroll
    for (int i = 0; i < 4; ++i)
#pragma unroll
        for (int u = 0; u < 4; ++u) acc[i][u] = 0ull;

#pragma unroll 4
    for (int k = 0; k < DIMK; ++k) {
        const float* wsk = &Ws[k * DIMK];
        ulonglong2 wa = *(const ulonglong2*)&wsk[c_base];
        ulonglong2 wb = *(const ulonglong2*)&wsk[c_base + 4];
#pragma unroll
        for (int i = 0; i < 4; ++i) {
            float xv = xs[(r_base + i) * XS_P + k];
            u64 x0 = pk2(xv, xv);
            acc[i][0] = fma2(x0, wa.x, acc[i][0]);
            acc[i][1] = fma2(x0, wa.y, acc[i][1]);
            acc[i][2] = fma2(x0, wb.x, acc[i][2]);
            acc[i][3] = fma2(x0, wb.y, acc[i][3]);
        }
    }

    float4 ba = *(const float4*)&b0[c_base];
    float4 bb = *(const float4*)&b0[c_base + 4];
#pragma unroll
    for (int i = 0; i < 4; ++i) {
        int grow = row0 + r_base + i;
        if (grow < n) {
            float2 p0 = upk2(acc[i][0]), p1 = upk2(acc[i][1]);
            float2 p2 = upk2(acc[i][2]), p3 = upk2(acc[i][3]);
            float4 oa, ob;
            oa.x = fmaxf(p0.x + ba.x, 0.f); oa.y = fmaxf(p0.y + ba.y, 0.f);
            oa.z = fmaxf(p1.x + ba.z, 0.f); oa.w = fmaxf(p1.y + ba.w, 0.f);
            ob.x = fmaxf(p2.x + bb.x, 0.f); ob.y = fmaxf(p2.y + bb.y, 0.f);
            ob.z = fmaxf(p3.x + bb.z, 0.f); ob.w = fmaxf(p3.y + bb.w, 0.f);
            *(float4*)&g_h0[(size_t)grow * DIMK + c_base]     = oa;
            *(float4*)&g_h0[(size_t)grow * DIMK + c_base + 4] = ob;
        }
    }
}

// ---------------------------------------------------------------------------
// Scatter: one warp per edge; lane l moves float4 l of the 128-float row.
// ---------------------------------------------------------------------------
extern "C" __global__ void k_scatter(const int* __restrict__ ei, int nE)
{
    int gw   = (int)((blockIdx.x * blockDim.x + threadIdx.x) >> 5);
    int lane = threadIdx.x & 31;
    if (gw >= nE) return;
    int dst = ei[gw];        // edge_index[0][e] -> segment id
    int src = ei[nE + gw];   // edge_index[1][e] -> gathered features
    float4 v = *(const float4*)&g_h0[(size_t)src * DIMK + lane * 4];
    float* p = &g_agg[(size_t)dst * DIMK + lane * 4];
    asm volatile("red.global.add.v4.f32 [%0], {%1,%2,%3,%4};"
                 :: "l"(p), "f"(v.x), "f"(v.y), "f"(v.z), "f"(v.w) : "memory");
    if (lane == 0) atomicAdd(&g_deg[dst], 1.0f);
}

// ---------------------------------------------------------------------------
// GEMM2 fused: hin = h0 + agg/max(deg,1); h = relu(hin@W1^T + b1);
// logits = h@Wc^T + bc (classifier reduced via shfl + smem atomics).
// ---------------------------------------------------------------------------
extern "C" __global__ __launch_bounds__(512)
void k_gemm2(const float* __restrict__ W1, const float* __restrict__ b1,
             const float* __restrict__ Wc, const float* __restrict__ bc,
             float* __restrict__ out, int n)
{
    extern __shared__ float smem[];
    float* Ws  = smem;                       // 128*128
    float* xs  = smem + DIMK * DIMK;         // 128*132
    float* Wcs = xs + BM * XS_P;             // 4*128
    float* red = Wcs + NCLS * DIMK;          // 128*4
    const int tid  = threadIdx.x;
    const int row0 = blockIdx.x * BM;

#pragma unroll
    for (int it = 0; it < 8; ++it) {
        int idx = tid + it * 512;
        int j   = idx & 127;
        int k4  = (idx >> 7) * 4;
        float4 w = *(const float4*)&W1[j * DIMK + k4];
        Ws[(k4 + 0) * DIMK + j] = w.x;
        Ws[(k4 + 1) * DIMK + j] = w.y;
        Ws[(k4 + 2) * DIMK + j] = w.z;
        Ws[(k4 + 3) * DIMK + j] = w.w;
    }
    if (tid < 128) {
        float4 w = *(const float4*)&Wc[tid * 4];
        *(float4*)&Wcs[tid * 4] = w;
    }
    if (tid < BM * NCLS) red[tid] = bc[tid & 3];

    // hin tile: h0 + agg * (1/max(deg,1))
#pragma unroll
    for (int it = 0; it < 8; ++it) {
        int idx = tid + it * 512;
        int r   = idx >> 5;
        int c4  = (idx & 31) * 4;
        int grow = row0 + r;
        float4 v = make_float4(0.f, 0.f, 0.f, 0.f);
        if (grow < n) {
            float4 hv = *(const float4*)&g_h0[(size_t)grow * DIMK + c4];
            float4 av = *(const float4*)&g_agg[(size_t)grow * DIMK + c4];
            float inv = 1.0f / fmaxf(g_deg[grow], 1.0f);
            v.x = hv.x + av.x * inv;
            v.y = hv.y + av.y * inv;
            v.z = hv.z + av.z * inv;
            v.w = hv.w + av.w * inv;
        }
        *(float4*)&xs[r * XS_P + c4] = v;
    }
    __syncthreads();

    const int warp = tid >> 5, lane = tid & 31;
    const int warp_m = warp & 3, warp_n = warp >> 2;
    const int rgrp = lane >> 2, cgrp = lane & 3;
    const int r_base = warp_m * 32 + rgrp * 4;
    const int c_base = warp_n * 32 + cgrp * 8;

    u64 acc[4][4];
#pragma unroll
    for (int i = 0; i < 4; ++i)
#pragma unroll
        for (int u = 0; u < 4; ++u) acc[i][u] = 0ull;

#pragma unroll 4
    for (int k = 0; k < DIMK; ++k) {
        const float* wsk = &Ws[k * DIMK];
        ulonglong2 wa = *(const ulonglong2*)&wsk[c_base];
        ulonglong2 wb = *(const ulonglong2*)&wsk[c_base + 4];
#pragma unroll
        for (int i = 0; i < 4; ++i) {
            float xv = xs[(r_base + i) * XS_P + k];
            u64 x0 = pk2(xv, xv);
            acc[i][0] = fma2(x0, wa.x, acc[i][0]);
            acc[i][1] = fma2(x0, wa.y, acc[i][1]);
            acc[i][2] = fma2(x0, wb.x, acc[i][2]);
            acc[i][3] = fma2(x0, wb.y, acc[i][3]);
        }
    }

    float4 ba = *(const float4*)&b1[c_base];
    float4 bb = *(const float4*)&b1[c_base + 4];

    float part[4][NCLS];
#pragma unroll
    for (int i = 0; i < 4; ++i) {
        float h[8];
        float2 p0 = upk2(acc[i][0]), p1 = upk2(acc[i][1]);
        float2 p2 = upk2(acc[i][2]), p3 = upk2(acc[i][3]);
        h[0] = fmaxf(p0.x + ba.x, 0.f); h[1] = fmaxf(p0.y + ba.y, 0.f);
        h[2] = fmaxf(p1.x + ba.z, 0.f); h[3] = fmaxf(p1.y + ba.w, 0.f);
        h[4] = fmaxf(p2.x + bb.x, 0.f); h[5] = fmaxf(p2.y + bb.y, 0.f);
        h[6] = fmaxf(p3.x + bb.z, 0.f); h[7] = fmaxf(p3.y + bb.w, 0.f);
#pragma unroll
        for (int c = 0; c < NCLS; ++c) {
            const float* wrow = &Wcs[c * DIMK];
            float s = 0.f;
#pragma unroll
            for (int u = 0; u < 8; ++u) s += h[u] * wrow[c_base + u];
            part[i][c] = s;
        }
    }
    // Reduce over the 4 cgrp lanes.
#pragma unroll
    for (int i = 0; i < 4; ++i)
#pragma unroll
        for (int c = 0; c < NCLS; ++c) {
            float v = part[i][c];
            v += __shfl_xor_sync(0xffffffffu, v, 1);
            v += __shfl_xor_sync(0xffffffffu, v, 2);
            part[i][c] = v;
        }
    if (cgrp == 0) {
#pragma unroll
        for (int i = 0; i < 4; ++i) {
            int r = r_base + i;
#pragma unroll
            for (int c = 0; c < NCLS; ++c)
                atomicAdd(&red[r * NCLS + c], part[i][c]);
        }
    }
    __syncthreads();
    if (tid < BM) {
        int grow = row0 + tid;
        if (grow < n) {
            float4 o = *(const float4*)&red[tid * NCLS];
            *(float4*)&out[(size_t)grow * NCLS] = o;
        }
    }
}

extern "C" void kernel_launch(void* const* d_in, const int* in_sizes, int n_in,
                              void* d_out, int out_size)
{
    const float* x  = (const float*)d_in[0];
    const int*   ei = (const int*)  d_in[1];
    const float* W0 = (const float*)d_in[2];
    const float* b0 = (const float*)d_in[3];
    const float* W1 = (const float*)d_in[4];
    const float* b1 = (const float*)d_in[5];
    const float* Wc = (const float*)d_in[6];
    const float* bc = (const float*)d_in[7];
    float* out = (float*)d_out;

    int n  = in_sizes[0] / DIMK;     // 100000
    int nE = in_sizes[1] / 2;        // 800000

    int smem1 = (DIMK * DIMK + BM * XS_P) * (int)sizeof(float);
    int smem2 = (DIMK * DIMK + BM * XS_P + NCLS * DIMK + BM * NCLS) * (int)sizeof(float);
    cudaFuncSetAttribute(k_gemm1, cudaFuncAttributeMaxDynamicSharedMemorySize, smem1);
    cudaFuncSetAttribute(k_gemm2, cudaFuncAttributeMaxDynamicSharedMemorySize, smem2);

    int grid = (n + BM - 1) / BM;
    k_gemm1<<<grid, 512, smem1>>>(x, W0, b0, n);

    long long tthreads = (long long)nE * 32;
    int sblocks = (int)((tthreads + 255) / 256);
    k_scatter<<<sblocks, 256>>>(ei, nE);

    k_gemm2<<<grid, 512, smem2>>>(W1, b1, Wc, bc, out, n);
}